// round 15
// baseline (speedup 1.0000x reference)
#include <cuda_runtime.h>
#include <cuda_fp16.h>
#include <math.h>

#define NN  50000   // nodes
#define EE  800000  // edges
#define LL  100000  // label edges
#define HH  8       // heads
#define FD  32      // hidden
#define HC  256     // H*C
#define XST 36      // transposed xs row stride (floats): 144B, 16B-aligned rows

// ---------------- scratch (device globals) --------------------------------------
__device__ float  g_x[NN * FD];
__device__ __half g_hh[(size_t)NN * HC];
__device__ __half g_alsrc[NN * HH];         // fp16 attention logits (src part)
__device__ __half g_aldst[NN * HH];         // fp16 attention logits (dst part)
__device__ __half g_ale[2][(size_t)EE * HH];// fp16 edge logits (ea@M), CSR order, per layer
__device__ __half g_agg[(size_t)NN * HC];   // fp16 aggregation output
__device__ float  g_x5[NN * HH];
__device__ float  g_Psrc[2][FD * HH];
__device__ float  g_Pdst[2][FD * HH];
__device__ float  g_M[2][HH * HH];
// CSR by destination
__device__ int g_deg[NN];
__device__ int g_rowptr[NN + 1];
__device__ int g_cursor[NN];
__device__ int g_srcp[EE];   // src node per CSR slot
// degree-bucketed node order (load balance for agg)
__device__ int g_bins[64];
__device__ int g_binoff[64];
__device__ int g_bincur[64];
__device__ int g_order[NN];

// ------- precompute (blocks 0,1) + zero_deg/bins (blocks 2..): one launch ------
__global__ void k_pre_zero(const float* __restrict__ W1,  const float* __restrict__ as1,
                           const float* __restrict__ ad1, const float* __restrict__ We1,
                           const float* __restrict__ ae1,
                           const float* __restrict__ W2,  const float* __restrict__ as2,
                           const float* __restrict__ ad2, const float* __restrict__ We2,
                           const float* __restrict__ ae2)
{
    if (blockIdx.x >= 2) {
        int i = (blockIdx.x - 2) * 256 + threadIdx.x;
        if (i < NN) g_deg[i] = 0;
        if (blockIdx.x == 2 && threadIdx.x < 64) g_bins[threadIdx.x] = 0;
        return;
    }
    int layer = blockIdx.x;
    const float* W   = layer ? W2  : W1;
    const float* a_s = layer ? as2 : as1;
    const float* a_d = layer ? ad2 : ad1;
    const float* We  = layer ? We2 : We1;
    const float* a_e = layer ? ae2 : ae1;

    int t = threadIdx.x;           // 256 threads
    int f = t >> 3, h = t & 7;
    float ss = 0.f, sd = 0.f;
    #pragma unroll 8
    for (int c = 0; c < FD; c++) {
        float w = W[f * HC + h * FD + c];
        ss = fmaf(w, a_s[h * FD + c], ss);
        sd = fmaf(w, a_d[h * FD + c], sd);
    }
    g_Psrc[layer][f * HH + h] = ss;
    g_Pdst[layer][f * HH + h] = sd;
    if (t < 64) {
        int k = t >> 3;
        float sm = 0.f;
        #pragma unroll 8
        for (int c = 0; c < FD; c++)
            sm = fmaf(We[k * HC + h * FD + c], a_e[h * FD + c], sm);
        g_M[layer][k * HH + h] = sm;
    }
}

// ---------------- CSR build -----------------------------------------------------
__global__ void k_hist(const int* __restrict__ dst) {
    int e = blockIdx.x * 256 + threadIdx.x;
    if (e < EE) atomicAdd(&g_deg[dst[e]], 1);
}
__global__ void __launch_bounds__(1024)
k_scan(void) {
    const int CH = (NN + 1023) / 1024;   // 49
    __shared__ int sums[1024];
    int t = threadIdx.x;
    int base = t * CH;
    int s = 0;
    for (int i = 0; i < CH; i++) {
        int idx = base + i;
        if (idx < NN) s += g_deg[idx];
    }
    sums[t] = s;
    __syncthreads();
    for (int off = 1; off < 1024; off <<= 1) {
        int v = (t >= off) ? sums[t - off] : 0;
        __syncthreads();
        sums[t] += v;
        __syncthreads();
    }
    int run = (t > 0) ? sums[t - 1] : 0;
    for (int i = 0; i < CH; i++) {
        int idx = base + i;
        if (idx < NN) {
            g_rowptr[idx] = run;
            g_cursor[idx] = run;
            run += g_deg[idx];
        }
    }
    if (t == 1023) g_rowptr[NN] = run;
}

// ---- scatter fused with edge logits: srcp + both layers' ale -> CSR slot ------
__global__ void __launch_bounds__(256)
k_scatter_ale(const int* __restrict__ src, const int* __restrict__ dst,
              const float* __restrict__ ea)
{
    __shared__ float M0[64], M1[64];
    if (threadIdx.x < 64) {
        M0[threadIdx.x] = g_M[0][threadIdx.x];
        M1[threadIdx.x] = g_M[1][threadIdx.x];
    }
    __syncthreads();
    int e = blockIdx.x * 256 + threadIdx.x;
    if (e >= EE) return;
    int d = dst[e];
    int slot = atomicAdd(&g_cursor[d], 1);
    g_srcp[slot] = src[e];

    float4 e0 = *(const float4*)(ea + (size_t)e * 8);
    float4 e1 = *(const float4*)(ea + (size_t)e * 8 + 4);
    float ev[8] = { e0.x, e0.y, e0.z, e0.w, e1.x, e1.y, e1.z, e1.w };
    float a0[8], a1[8];
    #pragma unroll
    for (int h = 0; h < 8; h++) { a0[h] = 0.f; a1[h] = 0.f; }
    #pragma unroll
    for (int k = 0; k < 8; k++)
        #pragma unroll
        for (int h = 0; h < 8; h++) {
            a0[h] = fmaf(ev[k], M0[k * 8 + h], a0[h]);
            a1[h] = fmaf(ev[k], M1[k * 8 + h], a1[h]);
        }
    uint4 u0, u1;
    {
        __half2 t0 = __floats2half2_rn(a0[0], a0[1]);
        __half2 t1 = __floats2half2_rn(a0[2], a0[3]);
        __half2 t2 = __floats2half2_rn(a0[4], a0[5]);
        __half2 t3 = __floats2half2_rn(a0[6], a0[7]);
        u0.x = *(unsigned*)&t0; u0.y = *(unsigned*)&t1;
        u0.z = *(unsigned*)&t2; u0.w = *(unsigned*)&t3;
        __half2 s0 = __floats2half2_rn(a1[0], a1[1]);
        __half2 s1 = __floats2half2_rn(a1[2], a1[3]);
        __half2 s2 = __floats2half2_rn(a1[4], a1[5]);
        __half2 s3 = __floats2half2_rn(a1[6], a1[7]);
        u1.x = *(unsigned*)&s0; u1.y = *(unsigned*)&s1;
        u1.z = *(unsigned*)&s2; u1.w = *(unsigned*)&s3;
    }
    *(uint4*)(g_ale[0] + (size_t)slot * 8) = u0;
    *(uint4*)(g_ale[1] + (size_t)slot * 8) = u1;
}

// ---- degree-bucketed node ordering (counting sort, 64 bins, descending) -------
__global__ void k_obin(void) {
    int i = blockIdx.x * 256 + threadIdx.x;
    if (i < NN) {
        int b = g_deg[i]; if (b > 63) b = 63;
        atomicAdd(&g_bins[b], 1);
    }
}
__global__ void k_oscan(void) {
    if (threadIdx.x == 0) {
        int run = 0;
        for (int b = 63; b >= 0; b--) { g_binoff[b] = run; run += g_bins[b]; }
    }
    if (threadIdx.x < 64) g_bincur[threadIdx.x] = 0;
}
__global__ void k_oscat(void) {
    int i = blockIdx.x * 256 + threadIdx.x;
    if (i < NN) {
        int b = g_deg[i]; if (b > 63) b = 63;
        int pos = g_binoff[b] + atomicAdd(&g_bincur[b], 1);
        g_order[pos] = i;
    }
}

// ---------------- node transform: FFMA2 GEMM, transposed xs, LDS.128 ------------
__global__ void __launch_bounds__(256, 4)
k_node(const float* __restrict__ xin, const int* __restrict__ ids,
       const float* __restrict__ W, int layer)
{
    __shared__ float Ws[FD * HC];                 // 32KB, loaded once per 64 nodes
    __shared__ __align__(16) float xs[FD * XST];  // transposed: xs[k*XST + n]
    __shared__ float Ps[FD * HH], Pd[FD * HH];
    int t = threadIdx.x;

    for (int i = t; i < FD * HC; i += 256) Ws[i] = W[i];
    Ps[t] = g_Psrc[layer][t];
    Pd[t] = g_Pdst[layer][t];
    const float* xp = xin ? xin : g_x;

    for (int batch = 0; batch < 2; batch++) {
        int n0 = blockIdx.x * 64 + batch * 32;
        __syncthreads();
        for (int i = t; i < 32 * FD; i += 256) {
            int n = i >> 5, k = i & 31;
            int node = n0 + n;
            float v = 0.f;
            if (node < NN) {
                int r = ids ? ids[node] : node;
                v = xp[(size_t)r * FD + k];
            }
            xs[k * XST + n] = v;
        }
        __syncthreads();

        unsigned long long acc2[16];
        #pragma unroll
        for (int q = 0; q < 16; q++) acc2[q] = 0ull;
        #pragma unroll
        for (int k = 0; k < FD; k++) {
            float w = Ws[k * HC + t];
            unsigned long long w2;
            asm("mov.b64 %0, {%1, %1};" : "=l"(w2) : "f"(w));
            const ulonglong2* xr = (const ulonglong2*)&xs[k * XST]; // 16B-aligned
            #pragma unroll
            for (int q2 = 0; q2 < 8; q2++) {
                ulonglong2 xv = xr[q2];                 // broadcast LDS.128
                asm("fma.rn.f32x2 %0, %1, %2, %0;"
                    : "+l"(acc2[2 * q2])     : "l"(xv.x), "l"(w2));
                asm("fma.rn.f32x2 %0, %1, %2, %0;"
                    : "+l"(acc2[2 * q2 + 1]) : "l"(xv.y), "l"(w2));
            }
        }
        #pragma unroll
        for (int q = 0; q < 16; q++) {
            float lo, hi;
            asm("mov.b64 {%0, %1}, %2;" : "=f"(lo), "=f"(hi) : "l"(acc2[q]));
            int node = n0 + 2 * q;
            if (node < NN)     g_hh[(size_t)node * HC + t]       = __float2half(lo);
            if (node + 1 < NN) g_hh[(size_t)(node + 1) * HC + t] = __float2half(hi);
        }

        // attention matvecs (reads transposed xs)
        {
            int n = t >> 3, h = t & 7;
            if (n0 + n < NN) {
                float ss = 0.f, sd = 0.f;
                #pragma unroll
                for (int k = 0; k < FD; k++) {
                    float xv = xs[k * XST + n];
                    ss = fmaf(xv, Ps[k * HH + h], ss);
                    sd = fmaf(xv, Pd[k * HH + h], sd);
                }
                g_alsrc[(n0 + n) * HH + h] = __float2half(ss);
                g_aldst[(n0 + n) * HH + h] = __float2half(sd);
            }
        }
    }
}

// ---- heavy: agg[n] = (sum h[src]*ex) / (sum ex), weights built inline ----------
//      nodes taken via degree-bucketed order (warps in a block ~equal degree)
__global__ void __launch_bounds__(256)
k_agg_csr(int layer)
{
    int gw   = (blockIdx.x * 256 + threadIdx.x) >> 5;
    int lane = threadIdx.x & 31;
    if (gw >= NN) return;
    int n = g_order[gw];
    int r0 = g_rowptr[n], r1 = g_rowptr[n + 1];

    int head = lane >> 2;      // head owning cols lane*8 .. lane*8+7
    int hh   = lane & 7;       // head for weight compute
    int eg   = lane >> 3;      // weight-slot edge subgroup 0..3
    const __half* ale = layer ? g_ale[1] : g_ale[0];

    float ald = __half2float(g_aldst[(size_t)n * 8 + hh]);

    float acc0 = 0.f, acc1 = 0.f, acc2 = 0.f, acc3 = 0.f;
    float acc4 = 0.f, acc5 = 0.f, acc6 = 0.f, acc7 = 0.f;
    float dsum = 0.f;          // partial denom for head hh

    for (int p = r0; p < r1; p += 8) {
        int cnt = r1 - p;

        int sj[8];
        #pragma unroll
        for (int j = 0; j < 8; j++) {
            int pp = p + j; if (pp >= r1) pp = r1 - 1;
            sj[j] = g_srcp[pp];
        }
        int sA = (eg == 0) ? sj[0] : (eg == 1) ? sj[1] : (eg == 2) ? sj[2] : sj[3];
        int sB = (eg == 0) ? sj[4] : (eg == 1) ? sj[5] : (eg == 2) ? sj[6] : sj[7];

        // issue all h gathers back-to-back (MLP=8 per lane)
        uint4 v[8];
        #pragma unroll
        for (int j = 0; j < 8; j++)
            v[j] = *(const uint4*)(g_hh + (size_t)sj[j] * HC + lane * 8);

        size_t base = (size_t)p * 8;
        size_t lim  = (size_t)r1 * 8 - 1;
        size_t iA = base + lane;      if (iA > lim) iA = lim;
        size_t iB = base + 32 + lane; if (iB > lim) iB = lim;
        float aA = __half2float(ale[iA]) + __half2float(g_alsrc[(size_t)sA * 8 + hh]) + ald;
        float aB = __half2float(ale[iB]) + __half2float(g_alsrc[(size_t)sB * 8 + hh]) + ald;
        aA = aA > 0.f ? aA : 0.2f * aA;
        aB = aB > 0.f ? aB : 0.2f * aB;
        float w_a = __expf(aA);
        float w_b = __expf(aB);

        if (eg < cnt)     dsum += w_a;
        if (eg + 4 < cnt) dsum += w_b;

        #pragma unroll
        for (int j = 0; j < 8; j++) {
            float w = __shfl_sync(0xffffffffu, (j < 4) ? w_a : w_b,
                                  (j & 3) * 8 + head);
            if (j >= cnt) w = 0.f;
            float2 f0 = __half22float2(*(const __half2*)&v[j].x);
            float2 f1 = __half22float2(*(const __half2*)&v[j].y);
            float2 f2 = __half22float2(*(const __half2*)&v[j].z);
            float2 f3 = __half22float2(*(const __half2*)&v[j].w);
            acc0 = fmaf(f0.x, w, acc0); acc1 = fmaf(f0.y, w, acc1);
            acc2 = fmaf(f1.x, w, acc2); acc3 = fmaf(f1.y, w, acc3);
            acc4 = fmaf(f2.x, w, acc4); acc5 = fmaf(f2.y, w, acc5);
            acc6 = fmaf(f3.x, w, acc6); acc7 = fmaf(f3.y, w, acc7);
        }
    }
    dsum += __shfl_xor_sync(0xffffffffu, dsum, 8);
    dsum += __shfl_xor_sync(0xffffffffu, dsum, 16);
    float den  = __shfl_sync(0xffffffffu, dsum, head);
    float rinv = 1.f / (den + 1e-16f);

    __half2 o0 = __floats2half2_rn(acc0 * rinv, acc1 * rinv);
    __half2 o1 = __floats2half2_rn(acc2 * rinv, acc3 * rinv);
    __half2 o2 = __floats2half2_rn(acc4 * rinv, acc5 * rinv);
    __half2 o3 = __floats2half2_rn(acc6 * rinv, acc7 * rinv);
    uint4 uo;
    uo.x = *(unsigned*)&o0; uo.y = *(unsigned*)&o1;
    uo.z = *(unsigned*)&o2; uo.w = *(unsigned*)&o3;
    *(uint4*)(g_agg + (size_t)n * HC + lane * 8) = uo;
}

// ---------- epilogue: y = relu(agg + b) @ LW + lb (LW loaded ONCE per block) ----
template <int NJ, int BATCH>
__global__ void __launch_bounds__(256)
k_epi(const float* __restrict__ bias, const float* __restrict__ LW,
      const float* __restrict__ lb)
{
    constexpr int NODES = 256 / NJ;               // nodes per batch
    __shared__ float rows[NODES * 260];
    __shared__ float LWt[NJ * 260];               // transposed, padded stride
    int t = threadIdx.x;

    for (int i = t; i < HC * NJ; i += 256) {
        int c = i / NJ, j = i % NJ;
        LWt[j * 260 + c] = LW[i];
    }

    for (int b = 0; b < BATCH; b++) {
        int n0 = blockIdx.x * (NODES * BATCH) + b * NODES;
        __syncthreads();
        for (int i = t; i < NODES * HC; i += 256) {
            int n = i >> 8, c = i & 255;
            float v = 0.f;
            if (n0 + n < NN)
                v = __half2float(g_agg[(size_t)(n0 + n) * HC + c]) + bias[c];
            rows[n * 260 + c] = fmaxf(v, 0.f);
        }
        __syncthreads();

        int n = t / NJ, j = t % NJ;
        if (n0 + n < NN) {
            float acc = lb[j];
            #pragma unroll
            for (int c4 = 0; c4 < 64; c4++) {
                float4 r  = *(const float4*)&rows[n * 260 + c4 * 4];
                float4 wv = *(const float4*)&LWt[j * 260 + c4 * 4];
                acc = fmaf(r.x, wv.x, acc);
                acc = fmaf(r.y, wv.y, acc);
                acc = fmaf(r.z, wv.z, acc);
                acc = fmaf(r.w, wv.w, acc);
            }
            if (NJ == 32) g_x [(size_t)(n0 + n) * 32 + j] = acc;
            else          g_x5[(size_t)(n0 + n) * 8  + j] = acc;
        }
    }
}

// ---------------- classifier over label edges ---------------------------------
__global__ void __launch_bounds__(256)
k_clf(const int* __restrict__ eli, const float* __restrict__ ela,
      const float* __restrict__ cW, const float* __restrict__ cb,
      float* __restrict__ outp)
{
    __shared__ float Ws[128], Bs[8];
    if (threadIdx.x < 128) Ws[threadIdx.x] = cW[threadIdx.x];
    if (threadIdx.x < 8)   Bs[threadIdx.x] = cb[threadIdx.x];
    __syncthreads();
    int l = blockIdx.x * 256 + threadIdx.x;
    if (l >= LL) return;
    int u = eli[l], m = eli[LL + l];

    float4 u0 = *(const float4*)(g_x5 + (size_t)u * 8);
    float4 u1 = *(const float4*)(g_x5 + (size_t)u * 8 + 4);
    float4 m0 = *(const float4*)(g_x5 + (size_t)m * 8);
    float4 m1 = *(const float4*)(g_x5 + (size_t)m * 8 + 4);
    float4 a0 = *(const float4*)(ela + (size_t)l * 8);
    float4 a1 = *(const float4*)(ela + (size_t)l * 8 + 4);
    float xu[8] = { u0.x, u0.y, u0.z, u0.w, u1.x, u1.y, u1.z, u1.w };
    float xm[8] = { m0.x, m0.y, m0.z, m0.w, m1.x, m1.y, m1.z, m1.w };
    float ev[8] = { a0.x, a0.y, a0.z, a0.w, a1.x, a1.y, a1.z, a1.w };

    float dot = 0.f;
    #pragma unroll
    for (int j = 0; j < 8; j++) {
        float fu = Bs[j];
        #pragma unroll
        for (int k = 0; k < 8; k++) fu = fmaf(xu[k], Ws[k * 8 + j], fu);
        #pragma unroll
        for (int k = 0; k < 8; k++) fu = fmaf(ev[k], Ws[(8 + k) * 8 + j], fu);
        dot = fmaf(fu, xm[j], dot);
    }
    outp[l] = 1.f / (1.f + expf(-dot));
}

// ---------------- launch -------------------------------------------------------
extern "C" void kernel_launch(void* const* d_in, const int* in_sizes, int n_in,
                              void* d_out, int out_size)
{
    const int*   node_ids = (const int*)d_in[0];
    const int*   ei   = (const int*)d_in[1];
    const int*   eli  = (const int*)d_in[2];
    const float* ea   = (const float*)d_in[4];
    const float* ela  = (const float*)d_in[5];
    const float* emb  = (const float*)d_in[6];
    const float* W1   = (const float*)d_in[7];
    const float* as1  = (const float*)d_in[8];
    const float* ad1  = (const float*)d_in[9];
    const float* We1  = (const float*)d_in[10];
    const float* ae1  = (const float*)d_in[11];
    const float* b1   = (const float*)d_in[12];
    const float* l1W  = (const float*)d_in[13];
    const float* l1b  = (const float*)d_in[14];
    const float* W2   = (const float*)d_in[15];
    const float* as2  = (const float*)d_in[16];
    const float* ad2  = (const float*)d_in[17];
    const float* We2  = (const float*)d_in[18];
    const float* ae2  = (const float*)d_in[19];
    const float* b2   = (const float*)d_in[20];
    const float* l5W  = (const float*)d_in[21];
    const float* l5b  = (const float*)d_in[22];
    const float* cW   = (const float*)d_in[23];
    const float* cb   = (const float*)d_in[24];
    float* out = (float*)d_out;

    const int* srce = ei;
    const int* dste = ei + EE;

    const int GB_NODE = (NN + 63) / 64;            // 782 (64 nodes per block)
    const int GB_EDGE = (EE + 255) / 256;          // 3125
    const int GB_WARP = (NN * 32 + 255) / 256;     // 6250 (warp per node)
    const int GB_N256 = (NN + 255) / 256;          // 196
    const int GB_EPI1 = (NN + 63) / 64;            // 782 (8 nodes x 8 batches)
    const int GB_EPI2 = (NN + 127) / 128;          // 391 (32 nodes x 4 batches)

    // precompute (2 blocks) + zero_deg/bins (196 blocks) in one launch
    k_pre_zero<<<2 + GB_N256, 256>>>(W1, as1, ad1, We1, ae1, W2, as2, ad2, We2, ae2);
    k_hist<<<GB_EDGE, 256>>>(dste);
    k_scan<<<1, 1024>>>();
    // node1 stays 4th so the profiler's fixed capture lands on it
    k_node<<<GB_NODE, 256>>>(emb, node_ids, W1, 0);
    k_scatter_ale<<<GB_EDGE, 256>>>(srce, dste, ea);   // scatter + both layers' ale
    // degree-bucketed node order for agg load balance
    k_obin<<<GB_N256, 256>>>();
    k_oscan<<<1, 64>>>();
    k_oscat<<<GB_N256, 256>>>();

    // ---- layer 1 ----
    k_agg_csr<<<GB_WARP, 256>>>(0);
    k_epi<32, 8><<<GB_EPI1, 256>>>(b1, l1W, l1b);

    // ---- layer 2 ----
    k_node<<<GB_NODE, 256>>>(nullptr, nullptr, W2, 1);
    k_agg_csr<<<GB_WARP, 256>>>(1);
    k_epi<8, 4><<<GB_EPI2, 256>>>(b2, l5W, l5b);

    // ---- classifier ----
    k_clf<<<(LL + 255) / 256, 256>>>(eli, ela, cW, cb, out);
}

// round 16
// speedup vs baseline: 1.0465x; 1.0465x over previous
#include <cuda_runtime.h>
#include <cuda_fp16.h>
#include <math.h>

#define NN  50000   // nodes
#define EE  800000  // edges
#define LL  100000  // label edges
#define HH  8       // heads
#define FD  32      // hidden
#define HC  256     // H*C
#define XST 36      // transposed xs row stride (floats): 144B, 16B-aligned rows

// ---------------- scratch (device globals) --------------------------------------
__device__ float  g_x[NN * FD];
__device__ __half g_hh[(size_t)NN * HC];
__device__ __half g_alsrc[NN * HH];         // fp16 attention logits (src part)
__device__ __half g_aldst[NN * HH];         // fp16 attention logits (dst part)
__device__ __half g_ale[2][(size_t)EE * HH];// fp16 edge logits (ea@M), CSR order, per layer
__device__ __half g_agg[(size_t)NN * HC];   // fp16 aggregation output
__device__ float  g_x5[NN * HH];
__device__ float  g_Psrc[2][FD * HH];
__device__ float  g_Pdst[2][FD * HH];
__device__ float  g_M[2][HH * HH];
// CSR by destination
__device__ int g_deg[NN];
__device__ int g_rowptr[NN + 1];
__device__ int g_cursor[NN];
__device__ int g_srcp[EE];   // src node per CSR slot
__device__ int g_slot[EE];   // CSR slot per original edge

// ------- precompute (blocks 0,1) + zero_deg (blocks 2..): one launch -----------
__global__ void k_pre_zero(const float* __restrict__ W1,  const float* __restrict__ as1,
                           const float* __restrict__ ad1, const float* __restrict__ We1,
                           const float* __restrict__ ae1,
                           const float* __restrict__ W2,  const float* __restrict__ as2,
                           const float* __restrict__ ad2, const float* __restrict__ We2,
                           const float* __restrict__ ae2)
{
    if (blockIdx.x >= 2) {
        int i = (blockIdx.x - 2) * 256 + threadIdx.x;
        if (i < NN) g_deg[i] = 0;
        return;
    }
    int layer = blockIdx.x;
    const float* W   = layer ? W2  : W1;
    const float* a_s = layer ? as2 : as1;
    const float* a_d = layer ? ad2 : ad1;
    const float* We  = layer ? We2 : We1;
    const float* a_e = layer ? ae2 : ae1;

    int t = threadIdx.x;           // 256 threads
    int f = t >> 3, h = t & 7;
    float ss = 0.f, sd = 0.f;
    #pragma unroll 8
    for (int c = 0; c < FD; c++) {
        float w = W[f * HC + h * FD + c];
        ss = fmaf(w, a_s[h * FD + c], ss);
        sd = fmaf(w, a_d[h * FD + c], sd);
    }
    g_Psrc[layer][f * HH + h] = ss;
    g_Pdst[layer][f * HH + h] = sd;
    if (t < 64) {
        int k = t >> 3;
        float sm = 0.f;
        #pragma unroll 8
        for (int c = 0; c < FD; c++)
            sm = fmaf(We[k * HC + h * FD + c], a_e[h * FD + c], sm);
        g_M[layer][k * HH + h] = sm;
    }
}

// ---------------- CSR build -----------------------------------------------------
__global__ void k_hist(const int* __restrict__ dst) {
    int e = blockIdx.x * 256 + threadIdx.x;
    if (e < EE) atomicAdd(&g_deg[dst[e]], 1);
}
__global__ void __launch_bounds__(1024)
k_scan(void) {
    const int CH = (NN + 1023) / 1024;   // 49
    __shared__ int sums[1024];
    int t = threadIdx.x;
    int base = t * CH;
    int s = 0;
    for (int i = 0; i < CH; i++) {
        int idx = base + i;
        if (idx < NN) s += g_deg[idx];
    }
    sums[t] = s;
    __syncthreads();
    for (int off = 1; off < 1024; off <<= 1) {
        int v = (t >= off) ? sums[t - off] : 0;
        __syncthreads();
        sums[t] += v;
        __syncthreads();
    }
    int run = (t > 0) ? sums[t - 1] : 0;
    for (int i = 0; i < CH; i++) {
        int idx = base + i;
        if (idx < NN) {
            g_rowptr[idx] = run;
            g_cursor[idx] = run;
            run += g_deg[idx];
        }
    }
    if (t == 1023) g_rowptr[NN] = run;
}
__global__ void k_scatter(const int* __restrict__ src, const int* __restrict__ dst) {
    int e = blockIdx.x * 256 + threadIdx.x;
    if (e >= EE) return;
    int d = dst[e];
    int slot = atomicAdd(&g_cursor[d], 1);
    g_srcp[slot] = src[e];   // scattered store
    g_slot[e]    = slot;     // coalesced store
}

// ------- edge logits for BOTH layers, once: ale = ea@M -> CSR slot, fp16 -------
__global__ void __launch_bounds__(256)
k_edge_ale(const float* __restrict__ ea)
{
    __shared__ float M0[64], M1[64];
    if (threadIdx.x < 64) {
        M0[threadIdx.x] = g_M[0][threadIdx.x];
        M1[threadIdx.x] = g_M[1][threadIdx.x];
    }
    __syncthreads();
    int e = blockIdx.x * 256 + threadIdx.x;
    if (e >= EE) return;
    int p = g_slot[e];

    float4 e0 = *(const float4*)(ea + (size_t)e * 8);
    float4 e1 = *(const float4*)(ea + (size_t)e * 8 + 4);
    float ev[8] = { e0.x, e0.y, e0.z, e0.w, e1.x, e1.y, e1.z, e1.w };
    float a0[8], a1[8];
    #pragma unroll
    for (int h = 0; h < 8; h++) { a0[h] = 0.f; a1[h] = 0.f; }
    #pragma unroll
    for (int k = 0; k < 8; k++)
        #pragma unroll
        for (int h = 0; h < 8; h++) {
            a0[h] = fmaf(ev[k], M0[k * 8 + h], a0[h]);
            a1[h] = fmaf(ev[k], M1[k * 8 + h], a1[h]);
        }
    uint4 u0, u1;
    {
        __half2 t0 = __floats2half2_rn(a0[0], a0[1]);
        __half2 t1 = __floats2half2_rn(a0[2], a0[3]);
        __half2 t2 = __floats2half2_rn(a0[4], a0[5]);
        __half2 t3 = __floats2half2_rn(a0[6], a0[7]);
        u0.x = *(unsigned*)&t0; u0.y = *(unsigned*)&t1;
        u0.z = *(unsigned*)&t2; u0.w = *(unsigned*)&t3;
        __half2 s0 = __floats2half2_rn(a1[0], a1[1]);
        __half2 s1 = __floats2half2_rn(a1[2], a1[3]);
        __half2 s2 = __floats2half2_rn(a1[4], a1[5]);
        __half2 s3 = __floats2half2_rn(a1[6], a1[7]);
        u1.x = *(unsigned*)&s0; u1.y = *(unsigned*)&s1;
        u1.z = *(unsigned*)&s2; u1.w = *(unsigned*)&s3;
    }
    *(uint4*)(g_ale[0] + (size_t)p * 8) = u0;
    *(uint4*)(g_ale[1] + (size_t)p * 8) = u1;
}

// ---------------- node transform: FFMA2 GEMM, transposed xs, LDS.128 ------------
__global__ void __launch_bounds__(256, 4)
k_node(const float* __restrict__ xin, const int* __restrict__ ids,
       const float* __restrict__ W, int layer)
{
    __shared__ float Ws[FD * HC];                 // 32KB, loaded once per 64 nodes
    __shared__ __align__(16) float xs[FD * XST];  // transposed: xs[k*XST + n]
    __shared__ float Ps[FD * HH], Pd[FD * HH];
    int t = threadIdx.x;

    for (int i = t; i < FD * HC; i += 256) Ws[i] = W[i];
    Ps[t] = g_Psrc[layer][t];
    Pd[t] = g_Pdst[layer][t];
    const float* xp = xin ? xin : g_x;

    for (int batch = 0; batch < 2; batch++) {
        int n0 = blockIdx.x * 64 + batch * 32;
        __syncthreads();
        for (int i = t; i < 32 * FD; i += 256) {
            int n = i >> 5, k = i & 31;
            int node = n0 + n;
            float v = 0.f;
            if (node < NN) {
                int r = ids ? ids[node] : node;
                v = xp[(size_t)r * FD + k];
            }
            xs[k * XST + n] = v;
        }
        __syncthreads();

        unsigned long long acc2[16];
        #pragma unroll
        for (int q = 0; q < 16; q++) acc2[q] = 0ull;
        #pragma unroll
        for (int k = 0; k < FD; k++) {
            float w = Ws[k * HC + t];
            unsigned long long w2;
            asm("mov.b64 %0, {%1, %1};" : "=l"(w2) : "f"(w));
            const ulonglong2* xr = (const ulonglong2*)&xs[k * XST]; // 16B-aligned
            #pragma unroll
            for (int q2 = 0; q2 < 8; q2++) {
                ulonglong2 xv = xr[q2];                 // broadcast LDS.128
                asm("fma.rn.f32x2 %0, %1, %2, %0;"
                    : "+l"(acc2[2 * q2])     : "l"(xv.x), "l"(w2));
                asm("fma.rn.f32x2 %0, %1, %2, %0;"
                    : "+l"(acc2[2 * q2 + 1]) : "l"(xv.y), "l"(w2));
            }
        }
        #pragma unroll
        for (int q = 0; q < 16; q++) {
            float lo, hi;
            asm("mov.b64 {%0, %1}, %2;" : "=f"(lo), "=f"(hi) : "l"(acc2[q]));
            int node = n0 + 2 * q;
            if (node < NN)     g_hh[(size_t)node * HC + t]       = __float2half(lo);
            if (node + 1 < NN) g_hh[(size_t)(node + 1) * HC + t] = __float2half(hi);
        }

        // attention matvecs (reads transposed xs)
        {
            int n = t >> 3, h = t & 7;
            if (n0 + n < NN) {
                float ss = 0.f, sd = 0.f;
                #pragma unroll
                for (int k = 0; k < FD; k++) {
                    float xv = xs[k * XST + n];
                    ss = fmaf(xv, Ps[k * HH + h], ss);
                    sd = fmaf(xv, Pd[k * HH + h], sd);
                }
                g_alsrc[(n0 + n) * HH + h] = __float2half(ss);
                g_aldst[(n0 + n) * HH + h] = __float2half(sd);
            }
        }
    }
}

// ---- heavy: agg[n] = (sum h[src]*ex) / (sum ex), weights built inline ----------
//      ex = exp(lrelu(ale[CSR] + alsrc[src] + aldst[n]))
//      srcp fetched once per 8-edge group via broadcast + shfl (no redundant LDG)
__global__ void __launch_bounds__(256)
k_agg_csr(int layer)
{
    int n    = (blockIdx.x * 256 + threadIdx.x) >> 5;
    int lane = threadIdx.x & 31;
    if (n >= NN) return;
    int r0 = g_rowptr[n], r1 = g_rowptr[n + 1];

    int head = lane >> 2;      // head owning cols lane*8 .. lane*8+7
    int hh   = lane & 7;       // head for weight compute
    int eg   = lane >> 3;      // weight-slot edge subgroup 0..3
    const __half* ale = layer ? g_ale[1] : g_ale[0];

    float ald = __half2float(g_aldst[(size_t)n * 8 + hh]);

    float acc0 = 0.f, acc1 = 0.f, acc2 = 0.f, acc3 = 0.f;
    float acc4 = 0.f, acc5 = 0.f, acc6 = 0.f, acc7 = 0.f;
    float dsum = 0.f;          // partial denom for head hh

    for (int p = r0; p < r1; p += 8) {
        int cnt = r1 - p;

        // one srcp load per lane: lanes 0..7 hold srcp[p..p+7] (clamped); shfl out
        int pp = p + hh; if (pp >= r1) pp = r1 - 1;
        int sv = g_srcp[pp];
        int sj[8];
        #pragma unroll
        for (int j = 0; j < 8; j++)
            sj[j] = __shfl_sync(0xffffffffu, sv, j);
        int sA = __shfl_sync(0xffffffffu, sv, eg);
        int sB = __shfl_sync(0xffffffffu, sv, eg + 4);

        // issue all h gathers back-to-back (MLP=8 per lane)
        uint4 v[8];
        #pragma unroll
        for (int j = 0; j < 8; j++)
            v[j] = *(const uint4*)(g_hh + (size_t)sj[j] * HC + lane * 8);

        // edge logits (coalesced 64B per warp) + src logits (16B per edge group)
        size_t base = (size_t)p * 8;
        size_t lim  = (size_t)r1 * 8 - 1;
        size_t iA = base + lane;      if (iA > lim) iA = lim;
        size_t iB = base + 32 + lane; if (iB > lim) iB = lim;
        float aA = __half2float(ale[iA]) + __half2float(g_alsrc[(size_t)sA * 8 + hh]) + ald;
        float aB = __half2float(ale[iB]) + __half2float(g_alsrc[(size_t)sB * 8 + hh]) + ald;
        aA = aA > 0.f ? aA : 0.2f * aA;
        aB = aB > 0.f ? aB : 0.2f * aB;
        float w_a = __expf(aA);
        float w_b = __expf(aB);

        if (eg < cnt)     dsum += w_a;
        if (eg + 4 < cnt) dsum += w_b;

        #pragma unroll
        for (int j = 0; j < 8; j++) {
            float w = __shfl_sync(0xffffffffu, (j < 4) ? w_a : w_b,
                                  (j & 3) * 8 + head);
            if (j >= cnt) w = 0.f;
            float2 f0 = __half22float2(*(const __half2*)&v[j].x);
            float2 f1 = __half22float2(*(const __half2*)&v[j].y);
            float2 f2 = __half22float2(*(const __half2*)&v[j].z);
            float2 f3 = __half22float2(*(const __half2*)&v[j].w);
            acc0 = fmaf(f0.x, w, acc0); acc1 = fmaf(f0.y, w, acc1);
            acc2 = fmaf(f1.x, w, acc2); acc3 = fmaf(f1.y, w, acc3);
            acc4 = fmaf(f2.x, w, acc4); acc5 = fmaf(f2.y, w, acc5);
            acc6 = fmaf(f3.x, w, acc6); acc7 = fmaf(f3.y, w, acc7);
        }
    }
    // reduce denom across the 4 edge subgroups (lanes sharing hh)
    dsum += __shfl_xor_sync(0xffffffffu, dsum, 8);
    dsum += __shfl_xor_sync(0xffffffffu, dsum, 16);
    // lane k (k<8) now holds denom of head k
    float den  = __shfl_sync(0xffffffffu, dsum, head);
    float rinv = 1.f / (den + 1e-16f);

    // fp16 output: 16B per lane = full 512B row per warp
    __half2 o0 = __floats2half2_rn(acc0 * rinv, acc1 * rinv);
    __half2 o1 = __floats2half2_rn(acc2 * rinv, acc3 * rinv);
    __half2 o2 = __floats2half2_rn(acc4 * rinv, acc5 * rinv);
    __half2 o3 = __floats2half2_rn(acc6 * rinv, acc7 * rinv);
    uint4 uo;
    uo.x = *(unsigned*)&o0; uo.y = *(unsigned*)&o1;
    uo.z = *(unsigned*)&o2; uo.w = *(unsigned*)&o3;
    *(uint4*)(g_agg + (size_t)n * HC + lane * 8) = uo;
}

// ---------- epilogue: y = relu(agg + b) @ LW + lb (LW loaded ONCE per block) ----
template <int NJ, int BATCH>
__global__ void __launch_bounds__(256)
k_epi(const float* __restrict__ bias, const float* __restrict__ LW,
      const float* __restrict__ lb)
{
    constexpr int NODES = 256 / NJ;               // nodes per batch
    __shared__ float rows[NODES * 260];
    __shared__ float LWt[NJ * 260];               // transposed, padded stride
    int t = threadIdx.x;

    for (int i = t; i < HC * NJ; i += 256) {
        int c = i / NJ, j = i % NJ;
        LWt[j * 260 + c] = LW[i];
    }

    for (int b = 0; b < BATCH; b++) {
        int n0 = blockIdx.x * (NODES * BATCH) + b * NODES;
        __syncthreads();
        for (int i = t; i < NODES * HC; i += 256) {
            int n = i >> 8, c = i & 255;
            float v = 0.f;
            if (n0 + n < NN)
                v = __half2float(g_agg[(size_t)(n0 + n) * HC + c]) + bias[c];
            rows[n * 260 + c] = fmaxf(v, 0.f);
        }
        __syncthreads();

        int n = t / NJ, j = t % NJ;
        if (n0 + n < NN) {
            float acc = lb[j];
            #pragma unroll
            for (int c4 = 0; c4 < 64; c4++) {
                float4 r  = *(const float4*)&rows[n * 260 + c4 * 4];
                float4 wv = *(const float4*)&LWt[j * 260 + c4 * 4];
                acc = fmaf(r.x, wv.x, acc);
                acc = fmaf(r.y, wv.y, acc);
                acc = fmaf(r.z, wv.z, acc);
                acc = fmaf(r.w, wv.w, acc);
            }
            if (NJ == 32) g_x [(size_t)(n0 + n) * 32 + j] = acc;
            else          g_x5[(size_t)(n0 + n) * 8  + j] = acc;
        }
    }
}

// ---------------- classifier over label edges ---------------------------------
__global__ void __launch_bounds__(256)
k_clf(const int* __restrict__ eli, const float* __restrict__ ela,
      const float* __restrict__ cW, const float* __restrict__ cb,
      float* __restrict__ outp)
{
    __shared__ float Ws[128], Bs[8];
    if (threadIdx.x < 128) Ws[threadIdx.x] = cW[threadIdx.x];
    if (threadIdx.x < 8)   Bs[threadIdx.x] = cb[threadIdx.x];
    __syncthreads();
    int l = blockIdx.x * 256 + threadIdx.x;
    if (l >= LL) return;
    int u = eli[l], m = eli[LL + l];

    float4 u0 = *(const float4*)(g_x5 + (size_t)u * 8);
    float4 u1 = *(const float4*)(g_x5 + (size_t)u * 8 + 4);
    float4 m0 = *(const float4*)(g_x5 + (size_t)m * 8);
    float4 m1 = *(const float4*)(g_x5 + (size_t)m * 8 + 4);
    float4 a0 = *(const float4*)(ela + (size_t)l * 8);
    float4 a1 = *(const float4*)(ela + (size_t)l * 8 + 4);
    float xu[8] = { u0.x, u0.y, u0.z, u0.w, u1.x, u1.y, u1.z, u1.w };
    float xm[8] = { m0.x, m0.y, m0.z, m0.w, m1.x, m1.y, m1.z, m1.w };
    float ev[8] = { a0.x, a0.y, a0.z, a0.w, a1.x, a1.y, a1.z, a1.w };

    float dot = 0.f;
    #pragma unroll
    for (int j = 0; j < 8; j++) {
        float fu = Bs[j];
        #pragma unroll
        for (int k = 0; k < 8; k++) fu = fmaf(xu[k], Ws[k * 8 + j], fu);
        #pragma unroll
        for (int k = 0; k < 8; k++) fu = fmaf(ev[k], Ws[(8 + k) * 8 + j], fu);
        dot = fmaf(fu, xm[j], dot);
    }
    outp[l] = 1.f / (1.f + expf(-dot));
}

// ---------------- launch -------------------------------------------------------
extern "C" void kernel_launch(void* const* d_in, const int* in_sizes, int n_in,
                              void* d_out, int out_size)
{
    const int*   node_ids = (const int*)d_in[0];
    const int*   ei   = (const int*)d_in[1];
    const int*   eli  = (const int*)d_in[2];
    const float* ea   = (const float*)d_in[4];
    const float* ela  = (const float*)d_in[5];
    const float* emb  = (const float*)d_in[6];
    const float* W1   = (const float*)d_in[7];
    const float* as1  = (const float*)d_in[8];
    const float* ad1  = (const float*)d_in[9];
    const float* We1  = (const float*)d_in[10];
    const float* ae1  = (const float*)d_in[11];
    const float* b1   = (const float*)d_in[12];
    const float* l1W  = (const float*)d_in[13];
    const float* l1b  = (const float*)d_in[14];
    const float* W2   = (const float*)d_in[15];
    const float* as2  = (const float*)d_in[16];
    const float* ad2  = (const float*)d_in[17];
    const float* We2  = (const float*)d_in[18];
    const float* ae2  = (const float*)d_in[19];
    const float* b2   = (const float*)d_in[20];
    const float* l5W  = (const float*)d_in[21];
    const float* l5b  = (const float*)d_in[22];
    const float* cW   = (const float*)d_in[23];
    const float* cb   = (const float*)d_in[24];
    float* out = (float*)d_out;

    const int* srce = ei;
    const int* dste = ei + EE;

    const int GB_NODE = (NN + 63) / 64;            // 782 (64 nodes per block)
    const int GB_EDGE = (EE + 255) / 256;          // 3125
    const int GB_WARP = (NN * 32 + 255) / 256;     // 6250 (warp per node)
    const int GB_N256 = (NN + 255) / 256;          // 196
    const int GB_EPI1 = (NN + 63) / 64;            // 782 (8 nodes x 8 batches)
    const int GB_EPI2 = (NN + 127) / 128;          // 391 (32 nodes x 4 batches)

    // precompute (2 blocks) + zero_deg (196 blocks) in one launch
    k_pre_zero<<<2 + GB_N256, 256>>>(W1, as1, ad1, We1, ae1, W2, as2, ad2, We2, ae2);
    k_hist<<<GB_EDGE, 256>>>(dste);
    k_scan<<<1, 1024>>>();
    // node1 stays 4th so the profiler's fixed capture lands on it
    k_node<<<GB_NODE, 256>>>(emb, node_ids, W1, 0);
    k_scatter<<<GB_EDGE, 256>>>(srce, dste);
    k_edge_ale<<<GB_EDGE, 256>>>(ea);    // both layers' edge logits, once

    // ---- layer 1 ----
    k_agg_csr<<<GB_WARP, 256>>>(0);
    k_epi<32, 8><<<GB_EPI1, 256>>>(b1, l1W, l1b);

    // ---- layer 2 ----
    k_node<<<GB_NODE, 256>>>(nullptr, nullptr, W2, 1);
    k_agg_csr<<<GB_WARP, 256>>>(1);
    k_epi<8, 4><<<GB_EPI2, 256>>>(b2, l5W, l5b);

    // ---- classifier ----
    k_clf<<<(LL + 255) / 256, 256>>>(eli, ela, cW, cb, out);
}

// round 17
// speedup vs baseline: 1.1310x; 1.0807x over previous
#include <cuda_runtime.h>
#include <cuda_fp16.h>
#include <math.h>

#define NN  50000   // nodes
#define EE  800000  // edges
#define LL  100000  // label edges
#define HH  8       // heads
#define FD  32      // hidden
#define HC  256     // H*C
#define KST 40      // fp16 smem row stride (k-dim): 80B = 20 banks -> conflict-free quads

// ---------------- scratch (device globals) --------------------------------------
__device__ float  g_x[NN * FD];
__device__ __half g_hh[(size_t)NN * HC];
__device__ __half g_alsrc[NN * HH];         // fp16 attention logits (src part)
__device__ __half g_aldst[NN * HH];         // fp16 attention logits (dst part)
__device__ __half g_ale[2][(size_t)EE * HH];// fp16 edge logits (ea@M), CSR order, per layer
__device__ __half g_agg[(size_t)NN * HC];   // fp16 aggregation output
__device__ float  g_x5[NN * HH];
__device__ float  g_Psrc[2][FD * HH];
__device__ float  g_Pdst[2][FD * HH];
__device__ float  g_M[2][HH * HH];
// CSR by destination
__device__ int g_deg[NN];
__device__ int g_rowptr[NN + 1];
__device__ int g_cursor[NN];
__device__ int g_srcp[EE];   // src node per CSR slot
__device__ int g_slot[EE];   // CSR slot per original edge

// ------- precompute (blocks 0,1) + zero_deg (blocks 2..): one launch -----------
__global__ void k_pre_zero(const float* __restrict__ W1,  const float* __restrict__ as1,
                           const float* __restrict__ ad1, const float* __restrict__ We1,
                           const float* __restrict__ ae1,
                           const float* __restrict__ W2,  const float* __restrict__ as2,
                           const float* __restrict__ ad2, const float* __restrict__ We2,
                           const float* __restrict__ ae2)
{
    if (blockIdx.x >= 2) {
        int i = (blockIdx.x - 2) * 256 + threadIdx.x;
        if (i < NN) g_deg[i] = 0;
        return;
    }
    int layer = blockIdx.x;
    const float* W   = layer ? W2  : W1;
    const float* a_s = layer ? as2 : as1;
    const float* a_d = layer ? ad2 : ad1;
    const float* We  = layer ? We2 : We1;
    const float* a_e = layer ? ae2 : ae1;

    int t = threadIdx.x;           // 256 threads
    int f = t >> 3, h = t & 7;
    float ss = 0.f, sd = 0.f;
    #pragma unroll 8
    for (int c = 0; c < FD; c++) {
        float w = W[f * HC + h * FD + c];
        ss = fmaf(w, a_s[h * FD + c], ss);
        sd = fmaf(w, a_d[h * FD + c], sd);
    }
    g_Psrc[layer][f * HH + h] = ss;
    g_Pdst[layer][f * HH + h] = sd;
    if (t < 64) {
        int k = t >> 3;
        float sm = 0.f;
        #pragma unroll 8
        for (int c = 0; c < FD; c++)
            sm = fmaf(We[k * HC + h * FD + c], a_e[h * FD + c], sm);
        g_M[layer][k * HH + h] = sm;
    }
}

// ---------------- CSR build -----------------------------------------------------
__global__ void k_hist(const int* __restrict__ dst) {
    int e = blockIdx.x * 256 + threadIdx.x;
    if (e < EE) atomicAdd(&g_deg[dst[e]], 1);
}
__global__ void __launch_bounds__(1024)
k_scan(void) {
    const int CH = (NN + 1023) / 1024;   // 49
    __shared__ int sums[1024];
    int t = threadIdx.x;
    int base = t * CH;
    int s = 0;
    for (int i = 0; i < CH; i++) {
        int idx = base + i;
        if (idx < NN) s += g_deg[idx];
    }
    sums[t] = s;
    __syncthreads();
    for (int off = 1; off < 1024; off <<= 1) {
        int v = (t >= off) ? sums[t - off] : 0;
        __syncthreads();
        sums[t] += v;
        __syncthreads();
    }
    int run = (t > 0) ? sums[t - 1] : 0;
    for (int i = 0; i < CH; i++) {
        int idx = base + i;
        if (idx < NN) {
            g_rowptr[idx] = run;
            g_cursor[idx] = run;
            run += g_deg[idx];
        }
    }
    if (t == 1023) g_rowptr[NN] = run;
}
__global__ void k_scatter(const int* __restrict__ src, const int* __restrict__ dst) {
    int e = blockIdx.x * 256 + threadIdx.x;
    if (e >= EE) return;
    int d = dst[e];
    int slot = atomicAdd(&g_cursor[d], 1);
    g_srcp[slot] = src[e];   // scattered store
    g_slot[e]    = slot;     // coalesced store
}

// ------- edge logits for BOTH layers, once: ale = ea@M -> CSR slot, fp16 -------
__global__ void __launch_bounds__(256)
k_edge_ale(const float* __restrict__ ea)
{
    __shared__ float M0[64], M1[64];
    if (threadIdx.x < 64) {
        M0[threadIdx.x] = g_M[0][threadIdx.x];
        M1[threadIdx.x] = g_M[1][threadIdx.x];
    }
    __syncthreads();
    int e = blockIdx.x * 256 + threadIdx.x;
    if (e >= EE) return;
    int p = g_slot[e];

    float4 e0 = *(const float4*)(ea + (size_t)e * 8);
    float4 e1 = *(const float4*)(ea + (size_t)e * 8 + 4);
    float ev[8] = { e0.x, e0.y, e0.z, e0.w, e1.x, e1.y, e1.z, e1.w };
    float a0[8], a1[8];
    #pragma unroll
    for (int h = 0; h < 8; h++) { a0[h] = 0.f; a1[h] = 0.f; }
    #pragma unroll
    for (int k = 0; k < 8; k++)
        #pragma unroll
        for (int h = 0; h < 8; h++) {
            a0[h] = fmaf(ev[k], M0[k * 8 + h], a0[h]);
            a1[h] = fmaf(ev[k], M1[k * 8 + h], a1[h]);
        }
    uint4 u0, u1;
    {
        __half2 t0 = __floats2half2_rn(a0[0], a0[1]);
        __half2 t1 = __floats2half2_rn(a0[2], a0[3]);
        __half2 t2 = __floats2half2_rn(a0[4], a0[5]);
        __half2 t3 = __floats2half2_rn(a0[6], a0[7]);
        u0.x = *(unsigned*)&t0; u0.y = *(unsigned*)&t1;
        u0.z = *(unsigned*)&t2; u0.w = *(unsigned*)&t3;
        __half2 s0 = __floats2half2_rn(a1[0], a1[1]);
        __half2 s1 = __floats2half2_rn(a1[2], a1[3]);
        __half2 s2 = __floats2half2_rn(a1[4], a1[5]);
        __half2 s3 = __floats2half2_rn(a1[6], a1[7]);
        u1.x = *(unsigned*)&s0; u1.y = *(unsigned*)&s1;
        u1.z = *(unsigned*)&s2; u1.w = *(unsigned*)&s3;
    }
    *(uint4*)(g_ale[0] + (size_t)p * 8) = u0;
    *(uint4*)(g_ale[1] + (size_t)p * 8) = u1;
}

// ---------------- node transform: HMMA (mma.m16n8k16) GEMM ----------------------
// h[32 nodes, 256] = x16[32,32] @ W16[32,256]; warp w owns cols [w*32, w*32+32)
__global__ void __launch_bounds__(256, 4)
k_node(const float* __restrict__ xin, const int* __restrict__ ids,
       const float* __restrict__ W, int layer)
{
    __shared__ __align__(16) __half Wt[HC * KST];  // 20KB: Wt[col][k], stride KST
    __shared__ __align__(16) __half xs[32 * KST];  // 2.5KB: xs[node][k]
    __shared__ float Ps[FD * HH], Pd[FD * HH];
    int t = threadIdx.x;
    int w = t >> 5, lane = t & 31;
    int g = lane >> 2, tq = lane & 3;

    // W fp32 [k,c] -> fp16 transposed Wt[c][k] (once per block)
    for (int i = t; i < FD * HC; i += 256) {
        int k = i >> 8, c = i & 255;
        Wt[c * KST + k] = __float2half(W[i]);
    }
    Ps[t] = g_Psrc[layer][t];
    Pd[t] = g_Pdst[layer][t];
    const float* xp = xin ? xin : g_x;

    for (int batch = 0; batch < 2; batch++) {
        int n0 = blockIdx.x * 64 + batch * 32;
        __syncthreads();
        for (int i = t; i < 32 * FD; i += 256) {
            int n = i >> 5, k = i & 31;
            int node = n0 + n;
            float v = 0.f;
            if (node < NN) {
                int r = ids ? ids[node] : node;
                v = xp[(size_t)r * FD + k];
            }
            xs[n * KST + k] = __float2half(v);
        }
        __syncthreads();

        // acc[m][j][c]: m-tile (rows m*16..), n-tile j (cols w*32+8j..), frag c0..c3
        float acc[2][4][4];
        #pragma unroll
        for (int m = 0; m < 2; m++)
            #pragma unroll
            for (int j = 0; j < 4; j++)
                #pragma unroll
                for (int c = 0; c < 4; c++) acc[m][j][c] = 0.f;

        #pragma unroll
        for (int ks = 0; ks < 2; ks++) {
            int kb = ks * 16;
            unsigned a[2][4];
            #pragma unroll
            for (int m = 0; m < 2; m++) {
                int r0 = (m * 16 + g) * KST + kb + 2 * tq;
                int r1 = (m * 16 + g + 8) * KST + kb + 2 * tq;
                a[m][0] = *(const unsigned*)&xs[r0];
                a[m][1] = *(const unsigned*)&xs[r1];
                a[m][2] = *(const unsigned*)&xs[r0 + 8];
                a[m][3] = *(const unsigned*)&xs[r1 + 8];
            }
            #pragma unroll
            for (int j = 0; j < 4; j++) {
                int col = w * 32 + j * 8 + g;
                unsigned b0 = *(const unsigned*)&Wt[col * KST + kb + 2 * tq];
                unsigned b1 = *(const unsigned*)&Wt[col * KST + kb + 2 * tq + 8];
                #pragma unroll
                for (int m = 0; m < 2; m++) {
                    asm volatile(
                        "mma.sync.aligned.m16n8k16.row.col.f32.f16.f16.f32 "
                        "{%0,%1,%2,%3}, {%4,%5,%6,%7}, {%8,%9}, {%0,%1,%2,%3};"
                        : "+f"(acc[m][j][0]), "+f"(acc[m][j][1]),
                          "+f"(acc[m][j][2]), "+f"(acc[m][j][3])
                        : "r"(a[m][0]), "r"(a[m][1]), "r"(a[m][2]), "r"(a[m][3]),
                          "r"(b0), "r"(b1));
                }
            }
        }

        // store D fragments as fp16 pairs
        #pragma unroll
        for (int m = 0; m < 2; m++) {
            int rowA = n0 + m * 16 + g;
            int rowB = rowA + 8;
            #pragma unroll
            for (int j = 0; j < 4; j++) {
                int col = w * 32 + j * 8 + 2 * tq;
                if (rowA < NN) {
                    __half2 hv = __floats2half2_rn(acc[m][j][0], acc[m][j][1]);
                    *(__half2*)&g_hh[(size_t)rowA * HC + col] = hv;
                }
                if (rowB < NN) {
                    __half2 hv = __floats2half2_rn(acc[m][j][2], acc[m][j][3]);
                    *(__half2*)&g_hh[(size_t)rowB * HC + col] = hv;
                }
            }
        }

        // attention matvecs (from fp16 xs)
        {
            int n = t >> 3, h = t & 7;
            if (n0 + n < NN) {
                float ss = 0.f, sd = 0.f;
                #pragma unroll
                for (int k = 0; k < FD; k++) {
                    float xv = __half2float(xs[n * KST + k]);
                    ss = fmaf(xv, Ps[k * HH + h], ss);
                    sd = fmaf(xv, Pd[k * HH + h], sd);
                }
                g_alsrc[(n0 + n) * HH + h] = __float2half(ss);
                g_aldst[(n0 + n) * HH + h] = __float2half(sd);
            }
        }
    }
}

// ---- heavy: agg[n] = (sum h[src]*ex) / (sum ex), weights built inline ----------
//      ex = exp(lrelu(ale[CSR] + alsrc[src] + aldst[n]))
//      srcp fetched once per 8-edge group via broadcast + shfl (no redundant LDG)
__global__ void __launch_bounds__(256)
k_agg_csr(int layer)
{
    int n    = (blockIdx.x * 256 + threadIdx.x) >> 5;
    int lane = threadIdx.x & 31;
    if (n >= NN) return;
    int r0 = g_rowptr[n], r1 = g_rowptr[n + 1];

    int head = lane >> 2;      // head owning cols lane*8 .. lane*8+7
    int hh   = lane & 7;       // head for weight compute
    int eg   = lane >> 3;      // weight-slot edge subgroup 0..3
    const __half* ale = layer ? g_ale[1] : g_ale[0];

    float ald = __half2float(g_aldst[(size_t)n * 8 + hh]);

    float acc0 = 0.f, acc1 = 0.f, acc2 = 0.f, acc3 = 0.f;
    float acc4 = 0.f, acc5 = 0.f, acc6 = 0.f, acc7 = 0.f;
    float dsum = 0.f;          // partial denom for head hh

    for (int p = r0; p < r1; p += 8) {
        int cnt = r1 - p;

        int pp = p + hh; if (pp >= r1) pp = r1 - 1;
        int sv = g_srcp[pp];
        int sj[8];
        #pragma unroll
        for (int j = 0; j < 8; j++)
            sj[j] = __shfl_sync(0xffffffffu, sv, j);
        int sA = __shfl_sync(0xffffffffu, sv, eg);
        int sB = __shfl_sync(0xffffffffu, sv, eg + 4);

        uint4 v[8];
        #pragma unroll
        for (int j = 0; j < 8; j++)
            v[j] = *(const uint4*)(g_hh + (size_t)sj[j] * HC + lane * 8);

        size_t base = (size_t)p * 8;
        size_t lim  = (size_t)r1 * 8 - 1;
        size_t iA = base + lane;      if (iA > lim) iA = lim;
        size_t iB = base + 32 + lane; if (iB > lim) iB = lim;
        float aA = __half2float(ale[iA]) + __half2float(g_alsrc[(size_t)sA * 8 + hh]) + ald;
        float aB = __half2float(ale[iB]) + __half2float(g_alsrc[(size_t)sB * 8 + hh]) + ald;
        aA = aA > 0.f ? aA : 0.2f * aA;
        aB = aB > 0.f ? aB : 0.2f * aB;
        float w_a = __expf(aA);
        float w_b = __expf(aB);

        if (eg < cnt)     dsum += w_a;
        if (eg + 4 < cnt) dsum += w_b;

        #pragma unroll
        for (int j = 0; j < 8; j++) {
            float w = __shfl_sync(0xffffffffu, (j < 4) ? w_a : w_b,
                                  (j & 3) * 8 + head);
            if (j >= cnt) w = 0.f;
            float2 f0 = __half22float2(*(const __half2*)&v[j].x);
            float2 f1 = __half22float2(*(const __half2*)&v[j].y);
            float2 f2 = __half22float2(*(const __half2*)&v[j].z);
            float2 f3 = __half22float2(*(const __half2*)&v[j].w);
            acc0 = fmaf(f0.x, w, acc0); acc1 = fmaf(f0.y, w, acc1);
            acc2 = fmaf(f1.x, w, acc2); acc3 = fmaf(f1.y, w, acc3);
            acc4 = fmaf(f2.x, w, acc4); acc5 = fmaf(f2.y, w, acc5);
            acc6 = fmaf(f3.x, w, acc6); acc7 = fmaf(f3.y, w, acc7);
        }
    }
    dsum += __shfl_xor_sync(0xffffffffu, dsum, 8);
    dsum += __shfl_xor_sync(0xffffffffu, dsum, 16);
    float den  = __shfl_sync(0xffffffffu, dsum, head);
    float rinv = 1.f / (den + 1e-16f);

    __half2 o0 = __floats2half2_rn(acc0 * rinv, acc1 * rinv);
    __half2 o1 = __floats2half2_rn(acc2 * rinv, acc3 * rinv);
    __half2 o2 = __floats2half2_rn(acc4 * rinv, acc5 * rinv);
    __half2 o3 = __floats2half2_rn(acc6 * rinv, acc7 * rinv);
    uint4 uo;
    uo.x = *(unsigned*)&o0; uo.y = *(unsigned*)&o1;
    uo.z = *(unsigned*)&o2; uo.w = *(unsigned*)&o3;
    *(uint4*)(g_agg + (size_t)n * HC + lane * 8) = uo;
}

// ---------- epilogue: y = relu(agg + b) @ LW + lb (LW loaded ONCE per block) ----
template <int NJ, int BATCH>
__global__ void __launch_bounds__(256)
k_epi(const float* __restrict__ bias, const float* __restrict__ LW,
      const float* __restrict__ lb)
{
    constexpr int NODES = 256 / NJ;               // nodes per batch
    __shared__ float rows[NODES * 260];
    __shared__ float LWt[NJ * 260];               // transposed, padded stride
    int t = threadIdx.x;

    for (int i = t; i < HC * NJ; i += 256) {
        int c = i / NJ, j = i % NJ;
        LWt[j * 260 + c] = LW[i];
    }

    for (int b = 0; b < BATCH; b++) {
        int n0 = blockIdx.x * (NODES * BATCH) + b * NODES;
        __syncthreads();
        for (int i = t; i < NODES * HC; i += 256) {
            int n = i >> 8, c = i & 255;
            float v = 0.f;
            if (n0 + n < NN)
                v = __half2float(g_agg[(size_t)(n0 + n) * HC + c]) + bias[c];
            rows[n * 260 + c] = fmaxf(v, 0.f);
        }
        __syncthreads();

        int n = t / NJ, j = t % NJ;
        if (n0 + n < NN) {
            float acc = lb[j];
            #pragma unroll
            for (int c4 = 0; c4 < 64; c4++) {
                float4 r  = *(const float4*)&rows[n * 260 + c4 * 4];
                float4 wv = *(const float4*)&LWt[j * 260 + c4 * 4];
                acc = fmaf(r.x, wv.x, acc);
                acc = fmaf(r.y, wv.y, acc);
                acc = fmaf(r.z, wv.z, acc);
                acc = fmaf(r.w, wv.w, acc);
            }
            if (NJ == 32) g_x [(size_t)(n0 + n) * 32 + j] = acc;
            else          g_x5[(size_t)(n0 + n) * 8  + j] = acc;
        }
    }
}

// ---------------- classifier over label edges ---------------------------------
__global__ void __launch_bounds__(256)
k_clf(const int* __restrict__ eli, const float* __restrict__ ela,
      const float* __restrict__ cW, const float* __restrict__ cb,
      float* __restrict__ outp)
{
    __shared__ float Ws[128], Bs[8];
    if (threadIdx.x < 128) Ws[threadIdx.x] = cW[threadIdx.x];
    if (threadIdx.x < 8)   Bs[threadIdx.x] = cb[threadIdx.x];
    __syncthreads();
    int l = blockIdx.x * 256 + threadIdx.x;
    if (l >= LL) return;
    int u = eli[l], m = eli[LL + l];

    float4 u0 = *(const float4*)(g_x5 + (size_t)u * 8);
    float4 u1 = *(const float4*)(g_x5 + (size_t)u * 8 + 4);
    float4 m0 = *(const float4*)(g_x5 + (size_t)m * 8);
    float4 m1 = *(const float4*)(g_x5 + (size_t)m * 8 + 4);
    float4 a0 = *(const float4*)(ela + (size_t)l * 8);
    float4 a1 = *(const float4*)(ela + (size_t)l * 8 + 4);
    float xu[8] = { u0.x, u0.y, u0.z, u0.w, u1.x, u1.y, u1.z, u1.w };
    float xm[8] = { m0.x, m0.y, m0.z, m0.w, m1.x, m1.y, m1.z, m1.w };
    float ev[8] = { a0.x, a0.y, a0.z, a0.w, a1.x, a1.y, a1.z, a1.w };

    float dot = 0.f;
    #pragma unroll
    for (int j = 0; j < 8; j++) {
        float fu = Bs[j];
        #pragma unroll
        for (int k = 0; k < 8; k++) fu = fmaf(xu[k], Ws[k * 8 + j], fu);
        #pragma unroll
        for (int k = 0; k < 8; k++) fu = fmaf(ev[k], Ws[(8 + k) * 8 + j], fu);
        dot = fmaf(fu, xm[j], dot);
    }
    outp[l] = 1.f / (1.f + expf(-dot));
}

// ---------------- launch -------------------------------------------------------
extern "C" void kernel_launch(void* const* d_in, const int* in_sizes, int n_in,
                              void* d_out, int out_size)
{
    const int*   node_ids = (const int*)d_in[0];
    const int*   ei   = (const int*)d_in[1];
    const int*   eli  = (const int*)d_in[2];
    const float* ea   = (const float*)d_in[4];
    const float* ela  = (const float*)d_in[5];
    const float* emb  = (const float*)d_in[6];
    const float* W1   = (const float*)d_in[7];
    const float* as1  = (const float*)d_in[8];
    const float* ad1  = (const float*)d_in[9];
    const float* We1  = (const float*)d_in[10];
    const float* ae1  = (const float*)d_in[11];
    const float* b1   = (const float*)d_in[12];
    const float* l1W  = (const float*)d_in[13];
    const float* l1b  = (const float*)d_in[14];
    const float* W2   = (const float*)d_in[15];
    const float* as2  = (const float*)d_in[16];
    const float* ad2  = (const float*)d_in[17];
    const float* We2  = (const float*)d_in[18];
    const float* ae2  = (const float*)d_in[19];
    const float* b2   = (const float*)d_in[20];
    const float* l5W  = (const float*)d_in[21];
    const float* l5b  = (const float*)d_in[22];
    const float* cW   = (const float*)d_in[23];
    const float* cb   = (const float*)d_in[24];
    float* out = (float*)d_out;

    const int* srce = ei;
    const int* dste = ei + EE;

    const int GB_NODE = (NN + 63) / 64;            // 782 (64 nodes per block)
    const int GB_EDGE = (EE + 255) / 256;          // 3125
    const int GB_WARP = (NN * 32 + 255) / 256;     // 6250 (warp per node)
    const int GB_N256 = (NN + 255) / 256;          // 196
    const int GB_EPI1 = (NN + 63) / 64;            // 782 (8 nodes x 8 batches)
    const int GB_EPI2 = (NN + 127) / 128;          // 391 (32 nodes x 4 batches)

    // precompute (2 blocks) + zero_deg (196 blocks) in one launch
    k_pre_zero<<<2 + GB_N256, 256>>>(W1, as1, ad1, We1, ae1, W2, as2, ad2, We2, ae2);
    k_hist<<<GB_EDGE, 256>>>(dste);
    k_scan<<<1, 1024>>>();
    // node1 stays 4th so the profiler's fixed capture lands on it
    k_node<<<GB_NODE, 256>>>(emb, node_ids, W1, 0);
    k_scatter<<<GB_EDGE, 256>>>(srce, dste);
    k_edge_ale<<<GB_EDGE, 256>>>(ea);    // both layers' edge logits, once

    // ---- layer 1 ----
    k_agg_csr<<<GB_WARP, 256>>>(0);
    k_epi<32, 8><<<GB_EPI1, 256>>>(b1, l1W, l1b);

    // ---- layer 2 ----
    k_node<<<GB_NODE, 256>>>(nullptr, nullptr, W2, 1);
    k_agg_csr<<<GB_WARP, 256>>>(1);
    k_epi<8, 4><<<GB_EPI2, 256>>>(b2, l5W, l5b);

    // ---- classifier ----
    k_clf<<<(LL + 255) / 256, 256>>>(eli, ela, cW, cb, out);
}